// round 5
// baseline (speedup 1.0000x reference)
#include <cuda_runtime.h>
#include <math.h>
#include <float.h>

constexpr int Hh = 8;
constexpr int Jn = 22;
constexpr int Sn = 66;
#define NEGV (-9e15f)

// smem strides (floats) — A-side strides ODD (conflict-free column access)
constexpr int XS_STRIDE  = 257;  // 66 rows
constexpr int WS2_STRIDE = 516;  // 48 pair-rows of 256 float2 (+pad), 2064B
constexpr int QS_STRIDE  = 33;   // 66 rows
constexpr int KT_STRIDE  = 68;   // 32 rows (k transposed), 16B-aligned rows
constexpr int VS_STRIDE  = 34;   // 66 rows, 8B-aligned broadcasts
constexpr int PP_STRIDE  = 67;   // 66 rows
constexpr int OO_STRIDE  = 33;   // 68 rows (2 zero pad rows for cls tail)
constexpr int WC_STRIDE  = 68;   // 22 rows (2 zero pad cols)

constexpr int XS_OFF  = 0;
constexpr int WS2_OFF = 16964;   // 16B-aligned for cp.async
constexpr int QS_OFF  = WS2_OFF + 48 * WS2_STRIDE;     // 41732
constexpr int KT_OFF  = 43912;   // 16B-aligned rows
constexpr int VS_OFF  = KT_OFF + 32 * KT_STRIDE;       // 46088 (even)
constexpr int PP_OFF  = VS_OFF + 66 * VS_STRIDE;       // 48332
constexpr int OO_OFF  = PP_OFF + 66 * PP_STRIDE;       // 52754  (ends 54998)
constexpr int WC_OFF  = 55000;   // 16B-aligned
constexpr int SMEM_FLOATS = WC_OFF + 22 * WC_STRIDE;   // 56496 -> 225984 B

typedef unsigned long long ull;

// pre-paired weights: Wpk[h][p][k] = (Wcol(2p)[k], Wcol(2p+1)[k]), cols 0..95 = q|k|v
__device__ float2 g_Wpk[8 * 48 * 256];

__global__ void repack_weights(const float* __restrict__ Wq,
                               const float* __restrict__ Wk,
                               const float* __restrict__ Wv) {
    int i = blockIdx.x * blockDim.x + threadIdx.x;
    if (i >= 8 * 48 * 256) return;
    int k = i & 255;
    int p = (i >> 8) % 48;
    int h = i / (48 * 256);
    int n0 = 2 * p, n1 = 2 * p + 1;
    const float* W0 = (n0 < 32) ? Wq : (n0 < 64 ? Wk : Wv);
    const float* W1 = (n1 < 32) ? Wq : (n1 < 64 ? Wk : Wv);
    g_Wpk[i] = make_float2(W0[(h * 32 + (n0 & 31)) * 256 + k],
                           W1[(h * 32 + (n1 & 31)) * 256 + k]);
}

static __device__ __forceinline__ ull pk2(float a, float b) {
    ull r; asm("mov.b64 %0, {%1,%2};" : "=l"(r) : "f"(a), "f"(b)); return r;
}
static __device__ __forceinline__ void upk2(ull v, float &a, float &b) {
    asm("mov.b64 {%0,%1}, %2;" : "=f"(a), "=f"(b) : "l"(v));
}
static __device__ __forceinline__ ull ffma2(ull a, ull b, ull c) {
    ull d; asm("fma.rn.f32x2 %0, %1, %2, %3;" : "=l"(d) : "l"(a), "l"(b), "l"(c)); return d;
}
static __device__ __forceinline__ void cp16(unsigned int dst, const void* src) {
    asm volatile("cp.async.ca.shared.global [%0], [%1], 16;" :: "r"(dst), "l"(src));
}
static __device__ __forceinline__ void cp_commit() { asm volatile("cp.async.commit_group;"); }
static __device__ __forceinline__ void cp_wait0()  { asm volatile("cp.async.wait_group 0;"); }

__global__ __launch_bounds__(512, 1)
void mha_fused_kernel(const float* __restrict__ x,
                      const float* __restrict__ bq,
                      const float* __restrict__ bk,
                      const float* __restrict__ bv,
                      const float* __restrict__ Wc, const float* __restrict__ bc,
                      float* __restrict__ out)
{
    extern __shared__ float sm[];
    float* xs  = sm + XS_OFF;
    float* ws2 = sm + WS2_OFF;
    float* qs  = sm + QS_OFF;
    float* kt  = sm + KT_OFF;
    float* vs  = sm + VS_OFF;
    float* pp  = sm + PP_OFF;
    float* oo  = sm + OO_OFF;
    float* wcs = sm + WC_OFF;

    const int bt   = blockIdx.x;
    const int tid  = threadIdx.x;
    const int lane = tid & 31;
    const int wid  = tid >> 5;
    const int tm   = lane;

    const unsigned int sbase = (unsigned int)__cvta_generic_to_shared(sm);

    // ---- stage ws2 for head 0 via cp.async (aligned) ----
    {
        const float2* src = g_Wpk;  // h = 0
        for (int c = tid; c < 48 * 128; c += 512) {
            int row = c >> 7, ch = c & 127;
            cp16(sbase + (unsigned)(WS2_OFF + row * WS2_STRIDE + ch * 4) * 4,
                 src + row * 256 + ch * 2);
        }
    }
    cp_commit();

    // ---- stage x (scalar: coalesced LDG, conflict-free STS at odd stride) ----
    const float* xg = x + (size_t)bt * (Sn * 256);
    for (int t = tid; t < Sn * 256; t += 512) {
        int row = t >> 8, col = t & 255;
        xs[row * XS_STRIDE + col] = xg[t];
    }

    // ---- stage wcs (+zero pad cols), zero oo pad rows 66,67 (66 floats) ----
    for (int idx = tid; idx < 22 * 68; idx += 512) {
        int j = idx / 68, c = idx - j * 68;
        wcs[idx] = (c < 66) ? Wc[j * 66 + c] : 0.0f;
    }
    if (tid < 66) oo[66 * OO_STRIDE + tid] = 0.0f;   // rows 66 and 67 together

    const float scale = 0.17677669529663687f; // 1/sqrt(32)

    for (int h = 0; h < Hh; ++h) {
        cp_wait0();
        __syncthreads();   // ws2[h] (and x on h=0) visible to all

        // ================= QKV projection =================
        if (wid < 12) {
            // rows {tm, tm+32}, pairs p0..p0+3 (cols 2p0..2p0+7)
            const int p0 = wid * 4;
            ull acc[2][4];
            #pragma unroll
            for (int u = 0; u < 2; ++u)
                #pragma unroll
                for (int j = 0; j < 4; ++j) acc[u][j] = 0ULL;

            const float* xr0 = xs + tm * XS_STRIDE;
            const float* xr1 = xs + (tm + 32) * XS_STRIDE;
            const longlong2* w0 = reinterpret_cast<const longlong2*>(ws2 + (p0 + 0) * WS2_STRIDE);
            const longlong2* w1 = reinterpret_cast<const longlong2*>(ws2 + (p0 + 1) * WS2_STRIDE);
            const longlong2* w2 = reinterpret_cast<const longlong2*>(ws2 + (p0 + 2) * WS2_STRIDE);
            const longlong2* w3 = reinterpret_cast<const longlong2*>(ws2 + (p0 + 3) * WS2_STRIDE);

            #pragma unroll 4
            for (int kc = 0; kc < 128; ++kc) {   // 2 k's per iter
                longlong2 B0 = w0[kc], B1 = w1[kc], B2 = w2[kc], B3 = w3[kc];
                float a00 = xr0[2 * kc], a01 = xr0[2 * kc + 1];
                float a10 = xr1[2 * kc], a11 = xr1[2 * kc + 1];
                ull u00 = pk2(a00, a00), u01 = pk2(a01, a01);
                ull u10 = pk2(a10, a10), u11 = pk2(a11, a11);
                acc[0][0] = ffma2(u00, (ull)B0.x, acc[0][0]);
                acc[0][0] = ffma2(u01, (ull)B0.y, acc[0][0]);
                acc[0][1] = ffma2(u00, (ull)B1.x, acc[0][1]);
                acc[0][1] = ffma2(u01, (ull)B1.y, acc[0][1]);
                acc[0][2] = ffma2(u00, (ull)B2.x, acc[0][2]);
                acc[0][2] = ffma2(u01, (ull)B2.y, acc[0][2]);
                acc[0][3] = ffma2(u00, (ull)B3.x, acc[0][3]);
                acc[0][3] = ffma2(u01, (ull)B3.y, acc[0][3]);
                acc[1][0] = ffma2(u10, (ull)B0.x, acc[1][0]);
                acc[1][0] = ffma2(u11, (ull)B0.y, acc[1][0]);
                acc[1][1] = ffma2(u10, (ull)B1.x, acc[1][1]);
                acc[1][1] = ffma2(u11, (ull)B1.y, acc[1][1]);
                acc[1][2] = ffma2(u10, (ull)B2.x, acc[1][2]);
                acc[1][2] = ffma2(u11, (ull)B2.y, acc[1][2]);
                acc[1][3] = ffma2(u10, (ull)B3.x, acc[1][3]);
                acc[1][3] = ffma2(u11, (ull)B3.y, acc[1][3]);
            }

            #pragma unroll
            for (int u = 0; u < 2; ++u) {
                int r = tm + 32 * u;
                #pragma unroll
                for (int jp = 0; jp < 4; ++jp) {
                    float vlo, vhi;
                    upk2(acc[u][jp], vlo, vhi);
                    int n = 2 * (p0 + jp);
                    #pragma unroll
                    for (int e = 0; e < 2; ++e) {
                        int nn = n + e;
                        float val = (e == 0) ? vlo : vhi;
                        const float* bsrc = (nn < 32) ? bq : (nn < 64 ? bk : bv);
                        val += bsrc[h * 32 + (nn & 31)];
                        if (nn < 32)      qs[r * QS_STRIDE + nn] = val;
                        else if (nn < 64) kt[(nn - 32) * KT_STRIDE + r] = val;
                        else              vs[r * VS_STRIDE + (nn - 64)] = fmaxf(val, 0.0f);
                    }
                }
            }
        } else {
            // cleanup rows 64,65: warps 12-15, k-split per lane, warp-reduce.
            const int cw = wid - 12;
            for (int t = cw; t < 96; t += 4) {
                int row = 64 + (t & 1);
                int p = t >> 1;
                const float* xr = xs + row * XS_STRIDE;
                const ull* wp = reinterpret_cast<const ull*>(ws2 + p * WS2_STRIDE);
                ull acc = 0ULL;
                #pragma unroll
                for (int c = 0; c < 8; ++c) {
                    int k = c * 32 + lane;
                    float a = xr[k];
                    acc = ffma2(pk2(a, a), wp[k], acc);
                }
                float s0, s1;
                upk2(acc, s0, s1);
                #pragma unroll
                for (int o = 16; o; o >>= 1) {
                    s0 += __shfl_xor_sync(0xffffffffu, s0, o);
                    s1 += __shfl_xor_sync(0xffffffffu, s1, o);
                }
                if (lane == 0) {
                    #pragma unroll
                    for (int e = 0; e < 2; ++e) {
                        int nn = 2 * p + e;
                        float val = (e == 0) ? s0 : s1;
                        const float* bsrc = (nn < 32) ? bq : (nn < 64 ? bk : bv);
                        val += bsrc[h * 32 + (nn & 31)];
                        if (nn < 32)      qs[row * QS_STRIDE + nn] = val;
                        else if (nn < 64) kt[(nn - 32) * KT_STRIDE + row] = val;
                        else              vs[row * VS_STRIDE + (nn - 64)] = fmaxf(val, 0.0f);
                    }
                }
            }
        }
        __syncthreads();

        // prefetch next head's weights (hidden behind attention phases)
        if (h + 1 < Hh) {
            const float2* src = g_Wpk + (size_t)(h + 1) * (48 * 256);
            for (int c = tid; c < 48 * 128; c += 512) {
                int row = c >> 7, ch = c & 127;
                cp16(sbase + (unsigned)(WS2_OFF + row * WS2_STRIDE + ch * 4) * 4,
                     src + row * 256 + ch * 2);
            }
            cp_commit();
        }

        // ================= scores =================
        {
            int j0 = wid * 4;   // 16 warps x 4 cols = 64
            ull acc[2][2] = {{0ULL, 0ULL}, {0ULL, 0ULL}};
            const float* q0 = qs + tm * QS_STRIDE;
            const float* q1 = qs + (tm + 32) * QS_STRIDE;
            #pragma unroll 8
            for (int d = 0; d < 32; ++d) {
                longlong2 B = *reinterpret_cast<const longlong2*>(kt + d * KT_STRIDE + j0);
                float a0 = q0[d], a1 = q1[d];
                ull u0 = pk2(a0, a0), u1 = pk2(a1, a1);
                acc[0][0] = ffma2(u0, (ull)B.x, acc[0][0]);
                acc[0][1] = ffma2(u0, (ull)B.y, acc[0][1]);
                acc[1][0] = ffma2(u1, (ull)B.x, acc[1][0]);
                acc[1][1] = ffma2(u1, (ull)B.y, acc[1][1]);
            }
            #pragma unroll
            for (int u = 0; u < 2; ++u) {
                int i = tm + 32 * u;
                #pragma unroll
                for (int jp = 0; jp < 2; ++jp) {
                    float s0, s1;
                    upk2(acc[u][jp], s0, s1);
                    int j = j0 + 2 * jp;
                    bool m0 = (i < Jn && j     >= 2 * Jn) || (i >= 2 * Jn && j     < Jn);
                    bool m1 = (i < Jn && j + 1 >= 2 * Jn) || (i >= 2 * Jn && j + 1 < Jn);
                    pp[i * PP_STRIDE + j]     = m0 ? 0.0f : s0 * scale;
                    pp[i * PP_STRIDE + j + 1] = m1 ? 0.0f : s1 * scale;
                }
            }
        }
        if (tid < 260) {   // rows 64,65 all j; cols 64,65 for i<64
            int i, j;
            if (tid < 132) { i = 64 + tid / 66; j = tid % 66; }
            else { int t2 = tid - 132; i = t2 >> 1; j = 64 + (t2 & 1); }
            bool masked = (i < Jn && j >= 2 * Jn) || (i >= 2 * Jn && j < Jn);
            float s = 0.0f;
            if (!masked) {
                const float* qi = qs + i * QS_STRIDE;
                float d0 = 0.0f;
                #pragma unroll 8
                for (int d = 0; d < 32; ++d) d0 += qi[d] * kt[d * KT_STRIDE + j];
                s = d0 * scale;
            }
            pp[i * PP_STRIDE + j] = s;
        }
        __syncthreads();

        // ================= softmax with threshold pruning =================
        for (int r = wid; r < Sn; r += 16) {
            float* row = pp + r * PP_STRIDE;
            float v0 = row[lane];
            float v1 = row[lane + 32];
            float v2 = (lane < 2) ? row[lane + 64] : -FLT_MAX;
            float m = fmaxf(fmaxf(v0, v1), v2);
            #pragma unroll
            for (int o = 16; o; o >>= 1) m = fmaxf(m, __shfl_xor_sync(0xffffffffu, m, o));
            float thr = m * (1.0f / 9.0f);
            float t0 = (fabsf(v0) <= thr) ? NEGV : v0;
            float t1 = (fabsf(v1) <= thr) ? NEGV : v1;
            float t2v = (lane < 2) ? ((fabsf(v2) <= thr) ? NEGV : v2) : -FLT_MAX;
            float M2 = fmaxf(fmaxf(t0, t1), t2v);
            #pragma unroll
            for (int o = 16; o; o >>= 1) M2 = fmaxf(M2, __shfl_xor_sync(0xffffffffu, M2, o));
            float e0 = __expf(t0 - M2);
            float e1 = __expf(t1 - M2);
            float e2 = (lane < 2) ? __expf(t2v - M2) : 0.0f;
            float s = e0 + e1 + e2;
            #pragma unroll
            for (int o = 16; o; o >>= 1) s += __shfl_xor_sync(0xffffffffu, s, o);
            float inv = 1.0f / s;
            row[lane]      = e0 * inv;
            row[lane + 32] = e1 * inv;
            if (lane < 2) row[lane + 64] = e2 * inv;
        }
        __syncthreads();

        // ================= P @ V =================
        {
            int dd0 = wid * 2;
            ull acc0 = 0ULL, acc1 = 0ULL;
            const float* p0 = pp + tm * PP_STRIDE;
            const float* p1 = pp + (tm + 32) * PP_STRIDE;
            #pragma unroll 6
            for (int c = 0; c < Sn; ++c) {
                ull b = *reinterpret_cast<const ull*>(vs + c * VS_STRIDE + dd0);
                float a0 = p0[c], a1 = p1[c];
                acc0 = ffma2(pk2(a0, a0), b, acc0);
                acc1 = ffma2(pk2(a1, a1), b, acc1);
            }
            float r00, r01, r10, r11;
            upk2(acc0, r00, r01);
            upk2(acc1, r10, r11);
            oo[tm * OO_STRIDE + dd0]            = r00;
            oo[tm * OO_STRIDE + dd0 + 1]        = r01;
            oo[(tm + 32) * OO_STRIDE + dd0]     = r10;
            oo[(tm + 32) * OO_STRIDE + dd0 + 1] = r11;
        }
        if (tid < 64) {   // rows 64,65
            int row = 64 + (tid >= 32);
            int dd = tid & 31;
            const float* pr = pp + row * PP_STRIDE;
            float a = 0.0f;
            #pragma unroll 6
            for (int c = 0; c < Sn; ++c) a += pr[c] * vs[c * VS_STRIDE + dd];
            oo[row * OO_STRIDE + dd] = a;
        }
        __syncthreads();

        // ================= classifier + output =================
        const size_t obase = (size_t)bt * (Jn * 256) + (size_t)h * 32;
        for (int t = tid; t < Jn * 32; t += 512) {
            int j = t >> 5, dd = t & 31;
            const float4* wr = reinterpret_cast<const float4*>(wcs + j * WC_STRIDE);
            float a = bc[j];
            #pragma unroll
            for (int cc = 0; cc < 17; ++cc) {
                float4 w = wr[cc];
                const float* ob = oo + (4 * cc) * OO_STRIDE + dd;
                a += w.x * ob[0] + w.y * ob[OO_STRIDE]
                   + w.z * ob[2 * OO_STRIDE] + w.w * ob[3 * OO_STRIDE];
            }
            out[obase + (size_t)j * 256 + dd] = a;
        }
        __syncthreads();
    }
}

extern "C" void kernel_launch(void* const* d_in, const int* in_sizes, int n_in,
                              void* d_out, int out_size) {
    const float* x  = (const float*)d_in[0];
    const float* Wq = (const float*)d_in[1];
    const float* bq = (const float*)d_in[2];
    const float* Wk = (const float*)d_in[3];
    const float* bk = (const float*)d_in[4];
    const float* Wv = (const float*)d_in[5];
    const float* bv = (const float*)d_in[6];
    const float* Wc = (const float*)d_in[7];
    const float* bc = (const float*)d_in[8];
    float* out = (float*)d_out;

    repack_weights<<<(8 * 48 * 256 + 255) / 256, 256>>>(Wq, Wk, Wv);

    int blocks = in_sizes[0] / (Sn * 256);   // B*T = 3072
    size_t smem = (size_t)SMEM_FLOATS * sizeof(float);  // 225984 B
    cudaFuncSetAttribute(mha_fused_kernel,
                         cudaFuncAttributeMaxDynamicSharedMemorySize, (int)smem);
    mha_fused_kernel<<<blocks, 512, smem>>>(x, bq, bk, bv, Wc, bc, out);
}

// round 8
// speedup vs baseline: 1.5300x; 1.5300x over previous
#include <cuda_runtime.h>
#include <cuda_fp16.h>
#include <cstdint>
#include <math.h>
#include <float.h>

constexpr int Hh = 8;
constexpr int Jn = 22;
constexpr int Sn = 66;
#define NEGV (-9e15f)

// ---------------- smem byte layout ----------------
// fp16 tiles use 264-half rows (528B): row step = 132 words = 4 mod 32 -> frag loads conflict-free
constexpr int XH_OFF   = 0;        // x hi: 66 x 264 halfs = 34848
constexpr int XL_OFF   = 34848;    // x lo
constexpr int WH_OFF   = 69696;    // W hi: 96 x 264 halfs = 50688
constexpr int WL_OFF   = 120384;   // W lo
constexpr int KT_OFFB  = 171072;   // kt fp32 32x68
constexpr int VS_OFFB  = 179776;   // vs fp32 66x34
constexpr int QS_OFFB  = 188752;   // qs fp32 66x33
constexpr int PP_OFFB  = 197464;   // pp fp32 66x67
constexpr int OO_OFFB  = 215152;   // oo fp32 68x33 (2 pad rows)
constexpr int WC_OFFB  = 224128;   // wc fp32 22x68 (16B aligned)
constexpr int BIAS_OFFB= 230112;   // 96 floats
constexpr int SMEM_BYTES = 230496;

constexpr int QS_STRIDE = 33, KT_STRIDE = 68, VS_STRIDE = 34;
constexpr int PP_STRIDE = 67, OO_STRIDE = 33, WC_STRIDE = 68;

typedef unsigned long long ull;

// pre-split weights in global, [h][n][k] layout, scaled x16
__device__ __align__(16) __half g_Wh[8 * 96 * 256];
__device__ __align__(16) __half g_Wl[8 * 96 * 256];

__global__ void repack_weights(const float* __restrict__ Wq,
                               const float* __restrict__ Wk,
                               const float* __restrict__ Wv) {
    int i = blockIdx.x * blockDim.x + threadIdx.x;
    if (i >= 8 * 96 * 256) return;
    int k = i & 255;
    int n = (i >> 8) % 96;
    int h = i / (96 * 256);
    const float* Wsrc = (n < 32) ? Wq : (n < 64 ? Wk : Wv);
    float w = 16.0f * Wsrc[(h * 32 + (n & 31)) * 256 + k];
    __half hi = __float2half_rn(w);
    __half lo = __float2half_rn(w - __half2float(hi));
    g_Wh[i] = hi;
    g_Wl[i] = lo;
}

// ---------------- device helpers ----------------
static __device__ __forceinline__ ull pk2(float a, float b) {
    ull r; asm("mov.b64 %0, {%1,%2};" : "=l"(r) : "f"(a), "f"(b)); return r;
}
static __device__ __forceinline__ void upk2(ull v, float &a, float &b) {
    asm("mov.b64 {%0,%1}, %2;" : "=f"(a), "=f"(b) : "l"(v));
}
static __device__ __forceinline__ ull ffma2(ull a, ull b, ull c) {
    ull d; asm("fma.rn.f32x2 %0, %1, %2, %3;" : "=l"(d) : "l"(a), "l"(b), "l"(c)); return d;
}
static __device__ __forceinline__ void cp16(unsigned dst, const void* src) {
    asm volatile("cp.async.ca.shared.global [%0], [%1], 16;" :: "r"(dst), "l"(src));
}
static __device__ __forceinline__ void cp_commit() { asm volatile("cp.async.commit_group;"); }
static __device__ __forceinline__ void cp_wait0()  { asm volatile("cp.async.wait_group 0;"); }

static __device__ __forceinline__ void mma16816(float* c, const unsigned* a, const unsigned* b) {
    asm volatile("mma.sync.aligned.m16n8k16.row.col.f32.f16.f16.f32 "
        "{%0,%1,%2,%3}, {%4,%5,%6,%7}, {%8,%9}, {%0,%1,%2,%3};"
        : "+f"(c[0]), "+f"(c[1]), "+f"(c[2]), "+f"(c[3])
        : "r"(a[0]), "r"(a[1]), "r"(a[2]), "r"(a[3]), "r"(b[0]), "r"(b[1]));
}

__global__ __launch_bounds__(512, 1)
void mha_fused_kernel(const float* __restrict__ x,
                      const float* __restrict__ bq,
                      const float* __restrict__ bk,
                      const float* __restrict__ bv,
                      const float* __restrict__ Wc, const float* __restrict__ bc,
                      float* __restrict__ out)
{
    extern __shared__ float sm[];
    char* smc = reinterpret_cast<char*>(sm);
    float* kt  = reinterpret_cast<float*>(smc + KT_OFFB);
    float* vs  = reinterpret_cast<float*>(smc + VS_OFFB);
    float* qs  = reinterpret_cast<float*>(smc + QS_OFFB);
    float* pp  = reinterpret_cast<float*>(smc + PP_OFFB);
    float* oo  = reinterpret_cast<float*>(smc + OO_OFFB);
    float* wcs = reinterpret_cast<float*>(smc + WC_OFFB);
    float* biasArr = reinterpret_cast<float*>(smc + BIAS_OFFB);

    const int bt   = blockIdx.x;
    const int tid  = threadIdx.x;
    const int lane = tid & 31;
    const int wid  = tid >> 5;
    const int tm   = lane;

    const unsigned sbase = (unsigned)__cvta_generic_to_shared(smc);

    // ---- prologue: stage W(0) via cp.async ----
    {
        const char* srcH = reinterpret_cast<const char*>(g_Wh);
        const char* srcL = reinterpret_cast<const char*>(g_Wl);
        for (int c = tid; c < 6144; c += 512) {   // 2 x 96 rows x 32 chunks of 16B
            int half_sel = c >= 3072;
            int cc = c - (half_sel ? 3072 : 0);
            int n = cc >> 5, ch = cc & 31;
            const char* s = (half_sel ? srcL : srcH) + n * 512 + ch * 16;
            unsigned d = sbase + (half_sel ? WL_OFF : WH_OFF) + n * 528 + ch * 16;
            cp16(d, s);
        }
        cp_commit();
    }
    // ---- x fp32 -> fp16 hi/lo split into stride-264 tiles ----
    {
        const float* xg = x + (size_t)bt * (Sn * 256);
        for (int t = tid; t < Sn * 256; t += 512) {
            int r = t >> 8, k = t & 255;
            float xv = xg[t];
            __half hi = __float2half_rn(xv);
            __half lo = __float2half_rn(xv - __half2float(hi));
            *reinterpret_cast<__half*>(smc + XH_OFF + r * 528 + k * 2) = hi;
            *reinterpret_cast<__half*>(smc + XL_OFF + r * 528 + k * 2) = lo;
        }
    }
    // ---- wc (+pad cols), oo pad rows ----
    for (int idx = tid; idx < 22 * 68; idx += 512) {
        int j = idx / 68, c = idx - j * 68;
        wcs[idx] = (c < 66) ? Wc[j * 66 + c] : 0.0f;
    }
    if (tid < 66) oo[66 * OO_STRIDE + tid] = 0.0f;

    const float scale = 0.17677669529663687f; // 1/sqrt(32)

    for (int h = 0; h < Hh; ++h) {
        cp_wait0();
        if (tid < 96) {
            const float* bsrc = (tid < 32) ? bq : (tid < 64 ? bk : bv);
            biasArr[tid] = bsrc[h * 32 + (tid & 31)];
        }
        __syncthreads();   // W(h), bias (and x, wc on h=0) visible

        // ================= QKV projection via mma.sync (HMMA) =================
        // 20 jobs: 5 m-tiles (16 rows, clamped) x 4 n-tiles (24 cols)
        for (int t = wid; t < 20; t += 16) {
            int mt = t >> 2, nt = t & 3;
            int m0 = mt * 16, n0 = nt * 24;
            int g = lane >> 2, kq = (lane & 3) * 2;
            int r0 = m0 + g, r1 = r0 + 8;
            int r0c = (r0 < 66) ? r0 : 65;
            int r1c = (r1 < 66) ? r1 : 65;
            const char* xh0 = smc + XH_OFF + r0c * 528;
            const char* xh1 = smc + XH_OFF + r1c * 528;
            const char* xl0 = smc + XL_OFF + r0c * 528;
            const char* xl1 = smc + XL_OFF + r1c * 528;
            const char* wh0 = smc + WH_OFF + (n0 + g) * 528;
            const char* wh1 = wh0 + 8 * 528;
            const char* wh2 = wh0 + 16 * 528;
            const char* wl0 = smc + WL_OFF + (n0 + g) * 528;
            const char* wl1 = wl0 + 8 * 528;
            const char* wl2 = wl0 + 16 * 528;

            float acc[3][4];
            #pragma unroll
            for (int j = 0; j < 3; ++j)
                #pragma unroll
                for (int e = 0; e < 4; ++e) acc[j][e] = 0.0f;

            #pragma unroll
            for (int ks = 0; ks < 16; ++ks) {
                int off = (ks * 16 + kq) * 2;
                unsigned a[4], al[4];
                a[0]  = *reinterpret_cast<const unsigned*>(xh0 + off);
                a[1]  = *reinterpret_cast<const unsigned*>(xh1 + off);
                a[2]  = *reinterpret_cast<const unsigned*>(xh0 + off + 16);
                a[3]  = *reinterpret_cast<const unsigned*>(xh1 + off + 16);
                al[0] = *reinterpret_cast<const unsigned*>(xl0 + off);
                al[1] = *reinterpret_cast<const unsigned*>(xl1 + off);
                al[2] = *reinterpret_cast<const unsigned*>(xl0 + off + 16);
                al[3] = *reinterpret_cast<const unsigned*>(xl1 + off + 16);

                unsigned b[2], bl[2];
                b[0]  = *reinterpret_cast<const unsigned*>(wh0 + off);
                b[1]  = *reinterpret_cast<const unsigned*>(wh0 + off + 16);
                bl[0] = *reinterpret_cast<const unsigned*>(wl0 + off);
                bl[1] = *reinterpret_cast<const unsigned*>(wl0 + off + 16);
                mma16816(acc[0], a, b);
                mma16816(acc[0], a, bl);
                mma16816(acc[0], al, b);

                b[0]  = *reinterpret_cast<const unsigned*>(wh1 + off);
                b[1]  = *reinterpret_cast<const unsigned*>(wh1 + off + 16);
                bl[0] = *reinterpret_cast<const unsigned*>(wl1 + off);
                bl[1] = *reinterpret_cast<const unsigned*>(wl1 + off + 16);
                mma16816(acc[1], a, b);
                mma16816(acc[1], a, bl);
                mma16816(acc[1], al, b);

                b[0]  = *reinterpret_cast<const unsigned*>(wh2 + off);
                b[1]  = *reinterpret_cast<const unsigned*>(wh2 + off + 16);
                bl[0] = *reinterpret_cast<const unsigned*>(wl2 + off);
                bl[1] = *reinterpret_cast<const unsigned*>(wl2 + off + 16);
                mma16816(acc[2], a, b);
                mma16816(acc[2], a, bl);
                mma16816(acc[2], al, b);
            }

            // epilogue: x1/16, +bias, route q|kt|vs (relu on v)
            #pragma unroll
            for (int j = 0; j < 3; ++j) {
                int cb = n0 + 8 * j + kq;
                #pragma unroll
                for (int e = 0; e < 2; ++e) {
                    int col = cb + e;
                    float bb = biasArr[col];
                    float v0 = acc[j][e]     * 0.0625f + bb;
                    float v1 = acc[j][2 + e] * 0.0625f + bb;
                    if (col < 32) {
                        if (r0 < 66) qs[r0 * QS_STRIDE + col] = v0;
                        if (r1 < 66) qs[r1 * QS_STRIDE + col] = v1;
                    } else if (col < 64) {
                        if (r0 < 66) kt[(col - 32) * KT_STRIDE + r0] = v0;
                        if (r1 < 66) kt[(col - 32) * KT_STRIDE + r1] = v1;
                    } else {
                        if (r0 < 66) vs[r0 * VS_STRIDE + (col - 64)] = fmaxf(v0, 0.0f);
                        if (r1 < 66) vs[r1 * VS_STRIDE + (col - 64)] = fmaxf(v1, 0.0f);
                    }
                }
            }
        }
        __syncthreads();

        // ---- prefetch W(h+1), hidden behind attention phases ----
        if (h + 1 < Hh) {
            const char* srcH = reinterpret_cast<const char*>(g_Wh) + (size_t)(h + 1) * 49152;
            const char* srcL = reinterpret_cast<const char*>(g_Wl) + (size_t)(h + 1) * 49152;
            for (int c = tid; c < 6144; c += 512) {
                int half_sel = c >= 3072;
                int cc = c - (half_sel ? 3072 : 0);
                int n = cc >> 5, ch = cc & 31;
                const char* s = (half_sel ? srcL : srcH) + n * 512 + ch * 16;
                unsigned d = sbase + (half_sel ? WL_OFF : WH_OFF) + n * 528 + ch * 16;
                cp16(d, s);
            }
            cp_commit();
        }

        // ================= scores =================
        {
            int j0 = wid * 4;   // 16 warps x 4 cols = 64
            ull acc[2][2] = {{0ULL, 0ULL}, {0ULL, 0ULL}};
            const float* q0 = qs + tm * QS_STRIDE;
            const float* q1 = qs + (tm + 32) * QS_STRIDE;
            #pragma unroll 8
            for (int d = 0; d < 32; ++d) {
                longlong2 B = *reinterpret_cast<const longlong2*>(kt + d * KT_STRIDE + j0);
                float a0 = q0[d], a1 = q1[d];
                ull u0 = pk2(a0, a0), u1 = pk2(a1, a1);
                acc[0][0] = ffma2(u0, (ull)B.x, acc[0][0]);
                acc[0][1] = ffma2(u0, (ull)B.y, acc[0][1]);
                acc[1][0] = ffma2(u1, (ull)B.x, acc[1][0]);
                acc[1][1] = ffma2(u1, (ull)B.y, acc[1][1]);
            }
            #pragma unroll
            for (int u = 0; u < 2; ++u) {
                int i = tm + 32 * u;
                #pragma unroll
                for (int jp = 0; jp < 2; ++jp) {
                    float s0, s1;
                    upk2(acc[u][jp], s0, s1);
                    int j = j0 + 2 * jp;
                    bool m0 = (i < Jn && j     >= 2 * Jn) || (i >= 2 * Jn && j     < Jn);
                    bool m1 = (i < Jn && j + 1 >= 2 * Jn) || (i >= 2 * Jn && j + 1 < Jn);
                    pp[i * PP_STRIDE + j]     = m0 ? 0.0f : s0 * scale;
                    pp[i * PP_STRIDE + j + 1] = m1 ? 0.0f : s1 * scale;
                }
            }
        }
        if (tid < 260) {   // rows 64,65 all j; cols 64,65 for i<64
            int i, j;
            if (tid < 132) { i = 64 + tid / 66; j = tid % 66; }
            else { int t2 = tid - 132; i = t2 >> 1; j = 64 + (t2 & 1); }
            bool masked = (i < Jn && j >= 2 * Jn) || (i >= 2 * Jn && j < Jn);
            float s = 0.0f;
            if (!masked) {
                const float* qi = qs + i * QS_STRIDE;
                float d0 = 0.0f;
                #pragma unroll 8
                for (int d = 0; d < 32; ++d) d0 += qi[d] * kt[d * KT_STRIDE + j];
                s = d0 * scale;
            }
            pp[i * PP_STRIDE + j] = s;
        }
        __syncthreads();

        // ================= softmax with threshold pruning =================
        for (int r = wid; r < Sn; r += 16) {
            float* row = pp + r * PP_STRIDE;
            float v0 = row[lane];
            float v1 = row[lane + 32];
            float v2 = (lane < 2) ? row[lane + 64] : -FLT_MAX;
            float m = fmaxf(fmaxf(v0, v1), v2);
            #pragma unroll
            for (int o = 16; o; o >>= 1) m = fmaxf(m, __shfl_xor_sync(0xffffffffu, m, o));
            float thr = m * (1.0f / 9.0f);
            float t0 = (fabsf(v0) <= thr) ? NEGV : v0;
            float t1 = (fabsf(v1) <= thr) ? NEGV : v1;
            float t2v = (lane < 2) ? ((fabsf(v2) <= thr) ? NEGV : v2) : -FLT_MAX;
            float M2 = fmaxf(fmaxf(t0, t1), t2v);
            #pragma unroll
            for (int o = 16; o; o >>= 1) M2 = fmaxf(M2, __shfl_xor_sync(0xffffffffu, M2, o));
            float e0 = __expf(t0 - M2);
            float e1 = __expf(t1 - M2);
            float e2 = (lane < 2) ? __expf(t2v - M2) : 0.0f;
            float s = e0 + e1 + e2;
            #pragma unroll
            for (int o = 16; o; o >>= 1) s += __shfl_xor_sync(0xffffffffu, s, o);
            float inv = 1.0f / s;
            row[lane]      = e0 * inv;
            row[lane + 32] = e1 * inv;
            if (lane < 2) row[lane + 64] = e2 * inv;
        }
        __syncthreads();

        // ================= P @ V =================
        {
            int dd0 = wid * 2;
            ull acc0 = 0ULL, acc1 = 0ULL;
            const float* p0 = pp + tm * PP_STRIDE;
            const float* p1 = pp + (tm + 32) * PP_STRIDE;
            #pragma unroll 6
            for (int c = 0; c < Sn; ++c) {
                ull b = *reinterpret_cast<const ull*>(vs + c * VS_STRIDE + dd0);
                float a0 = p0[c], a1 = p1[c];
                acc0 = ffma2(pk2(a0, a0), b, acc0);
                acc1 = ffma2(pk2(a1, a1), b, acc1);
            }
            float r00, r01, r10, r11;
            upk2(acc0, r00, r01);
            upk2(acc1, r10, r11);
            oo[tm * OO_STRIDE + dd0]            = r00;
            oo[tm * OO_STRIDE + dd0 + 1]        = r01;
            oo[(tm + 32) * OO_STRIDE + dd0]     = r10;
            oo[(tm + 32) * OO_STRIDE + dd0 + 1] = r11;
        }
        if (tid < 64) {   // rows 64,65
            int row = 64 + (tid >= 32);
            int dd = tid & 31;
            const float* pr = pp + row * PP_STRIDE;
            float a = 0.0f;
            #pragma unroll 6
            for (int c = 0; c < Sn; ++c) a += pr[c] * vs[c * VS_STRIDE + dd];
            oo[row * OO_STRIDE + dd] = a;
        }
        __syncthreads();

        // ================= classifier + output =================
        const size_t obase = (size_t)bt * (Jn * 256) + (size_t)h * 32;
        for (int t = tid; t < Jn * 32; t += 512) {
            int j = t >> 5, dd = t & 31;
            const float4* wr = reinterpret_cast<const float4*>(wcs + j * WC_STRIDE);
            float a = bc[j];
            #pragma unroll
            for (int cc = 0; cc < 17; ++cc) {
                float4 w = wr[cc];
                const float* ob = oo + (4 * cc) * OO_STRIDE + dd;
                a += w.x * ob[0] + w.y * ob[OO_STRIDE]
                   + w.z * ob[2 * OO_STRIDE] + w.w * ob[3 * OO_STRIDE];
            }
            out[obase + (size_t)j * 256 + dd] = a;
        }
        __syncthreads();
    }
}

extern "C" void kernel_launch(void* const* d_in, const int* in_sizes, int n_in,
                              void* d_out, int out_size) {
    const float* x  = (const float*)d_in[0];
    const float* Wq = (const float*)d_in[1];
    const float* bq = (const float*)d_in[2];
    const float* Wk = (const float*)d_in[3];
    const float* bk = (const float*)d_in[4];
    const float* Wv = (const float*)d_in[5];
    const float* bv = (const float*)d_in[6];
    const float* Wc = (const float*)d_in[7];
    const float* bc = (const float*)d_in[8];
    float* out = (float*)d_out;

    repack_weights<<<(8 * 96 * 256 + 255) / 256, 256>>>(Wq, Wk, Wv);

    int blocks = in_sizes[0] / (Sn * 256);   // B*T = 3072
    cudaFuncSetAttribute(mha_fused_kernel,
                         cudaFuncAttributeMaxDynamicSharedMemorySize, SMEM_BYTES);
    mha_fused_kernel<<<blocks, 512, SMEM_BYTES>>>(x, bq, bk, bv, Wc, bc, out);
}